// round 1
// baseline (speedup 1.0000x reference)
#include <cuda_runtime.h>
#include <math.h>

#define CC   128      // centers
#define DD   64       // latent dim
#define EPSF 1e-6f
#define TINV 10.0f    // 1/TEMP
#define DTF  0.1f

__device__ float g_qpot;
__device__ float g_sum;

// ---------- packed f32x2 helpers (sm_100a) ----------
__device__ __forceinline__ unsigned long long f2_fma(unsigned long long a,
                                                     unsigned long long b,
                                                     unsigned long long c) {
    unsigned long long d;
    asm("fma.rn.f32x2 %0, %1, %2, %3;" : "=l"(d) : "l"(a), "l"(b), "l"(c));
    return d;
}
__device__ __forceinline__ unsigned long long f2_add(unsigned long long a,
                                                     unsigned long long b) {
    unsigned long long d;
    asm("add.rn.f32x2 %0, %1, %2;" : "=l"(d) : "l"(a), "l"(b));
    return d;
}
__device__ __forceinline__ unsigned long long f2_pack(float x, float y) {
    unsigned long long r;
    unsigned xu = __float_as_uint(x), yu = __float_as_uint(y);
    asm("mov.b64 %0, {%1, %2};" : "=l"(r) : "r"(xu), "r"(yu));
    return r;
}
__device__ __forceinline__ float f2_sum_halves(unsigned long long a) {
    unsigned lo, hi;
    asm("mov.b64 {%0, %1}, %2;" : "=r"(lo), "=r"(hi) : "l"(a));
    return __uint_as_float(lo) + __uint_as_float(hi);
}

// ---------- Kernel 1: query flow field + q_pot (1 block, 128 threads) ----------
__global__ void q_kernel(const float* __restrict__ q,
                         const float* __restrict__ centers,
                         const float* __restrict__ mus,
                         float* __restrict__ out) {
    __shared__ float qs[DD];
    __shared__ float w[CC];
    __shared__ float rp[4];
    int tid = threadIdx.x;

    if (tid < DD) qs[tid] = q[tid];
    __syncthreads();

    // thread j == center j
    const float* crow = centers + tid * DD;
    float mu = mus[tid];
    float r2 = 0.f;
    #pragma unroll
    for (int d = 0; d < DD; ++d) {
        float df = crow[d] - qs[d];
        r2 = fmaf(df, df, r2);
    }
    r2 = fmaxf(r2, 1e-12f);
    float r = sqrtf(r2);
    float potc = mu / (r + EPSF);          // exact eps form (cheap here)
    w[tid] = mu / (r * r * r + EPSF);

    // reduce q_pot over 128 threads
    #pragma unroll
    for (int o = 16; o; o >>= 1) potc += __shfl_xor_sync(0xFFFFFFFFu, potc, o);
    if ((tid & 31) == 0) rp[tid >> 5] = potc;
    __syncthreads();
    if (tid == 0) {
        g_qpot = rp[0] + rp[1] + rp[2] + rp[3];
        g_sum  = 0.f;                       // re-zero every replay
    }

    // field step: out[d] = q[d] + DT * sum_j w_j * (c_jd - q_d)
    if (tid < DD) {
        float qd = qs[tid];
        float s = 0.f;
        #pragma unroll 4
        for (int j = 0; j < CC; ++j)
            s = fmaf(w[j], centers[j * DD + tid] - qd, s);
        out[tid] = fmaf(DTF, s, qd);
    }
}

// ---------- Kernel 2: per-candidate potential + exp(logit) + partial sums ----------
__global__ __launch_bounds__(256)
void pot_kernel(const float* __restrict__ cand,
                const float* __restrict__ centers,
                const float* __restrict__ mus,
                float* __restrict__ att, int N) {
    __shared__ __align__(16) float scc[CC * DD];   // 32 KB, row-major centers
    __shared__ float scn[CC];                      // |c_j|^2
    __shared__ float smu[CC];
    __shared__ float rs[8];
    int tid = threadIdx.x;

    for (int idx = tid; idx < CC * DD; idx += 256) scc[idx] = centers[idx];
    if (tid < CC) smu[tid] = mus[tid];
    __syncthreads();
    if (tid < CC) {
        const float* row = scc + tid * DD;
        float s = 0.f;
        #pragma unroll
        for (int d = 0; d < DD; ++d) s = fmaf(row[d], row[d], s);
        scn[tid] = s;
    }
    __syncthreads();

    int i  = blockIdx.x * 256 + tid;
    int ri = min(i, N - 1);

    // candidate row -> packed dim-pairs in registers (+ its squared norm)
    unsigned long long zp[DD / 2];
    const float4* zr = (const float4*)(cand + (size_t)ri * DD);
    float zn = 0.f;
    #pragma unroll
    for (int k = 0; k < DD / 4; ++k) {
        float4 v = zr[k];
        zn = fmaf(v.x, v.x, fmaf(v.y, v.y, fmaf(v.z, v.z, fmaf(v.w, v.w, zn))));
        zp[2 * k]     = f2_pack(v.x, v.y);
        zp[2 * k + 1] = f2_pack(v.z, v.w);
    }

    float qpot = g_qpot;
    float pot  = 0.f;
    const ulonglong2* sv = (const ulonglong2*)scc;  // 16 ulonglong2 per center row

    #pragma unroll 2
    for (int j = 0; j < CC; ++j) {
        const ulonglong2* row = sv + j * (DD / 4);
        unsigned long long a[4] = {0ull, 0ull, 0ull, 0ull};
        #pragma unroll
        for (int k = 0; k < DD / 4; ++k) {
            ulonglong2 cc = row[k];                 // one LDS.128 broadcast
            a[(2 * k) & 3]     = f2_fma(zp[2 * k],     cc.x, a[(2 * k) & 3]);
            a[(2 * k + 1) & 3] = f2_fma(zp[2 * k + 1], cc.y, a[(2 * k + 1) & 3]);
        }
        unsigned long long s = f2_add(f2_add(a[0], a[1]), f2_add(a[2], a[3]));
        float dot = f2_sum_halves(s);
        float d2 = fmaf(dot, -2.0f, zn + scn[j]);
        d2 = fmaxf(d2, 1e-12f);
        // mu/(sqrt(d2)+eps) ~= mu*rsqrt(d2)  (rel err ~eps/d ~ 1e-7)
        pot = fmaf(smu[j], rsqrtf(d2), pot);
    }

    float e = 0.f;
    if (i < N) {
        e = __expf(-TINV * fabsf(qpot - pot));      // logits <= 0: no max pass needed
        att[i] = e;
    }

    // block reduce e -> atomicAdd
    float bs = e;
    #pragma unroll
    for (int o = 16; o; o >>= 1) bs += __shfl_xor_sync(0xFFFFFFFFu, bs, o);
    if ((tid & 31) == 0) rs[tid >> 5] = bs;
    __syncthreads();
    if (tid < 8) {
        float v = rs[tid];
        #pragma unroll
        for (int o = 4; o; o >>= 1) v += __shfl_xor_sync(0x000000FFu, v, o);
        if (tid == 0) atomicAdd(&g_sum, v);
    }
}

// ---------- Kernel 3: normalize ----------
__global__ void norm_kernel(float* __restrict__ att, int N) {
    int i = blockIdx.x * blockDim.x + threadIdx.x;
    if (i < N) {
        float inv = 1.0f / g_sum;
        att[i] *= inv;
    }
}

extern "C" void kernel_launch(void* const* d_in, const int* in_sizes, int n_in,
                              void* d_out, int out_size) {
    const float* q       = (const float*)d_in[0];
    const float* cand    = (const float*)d_in[1];
    const float* centers = (const float*)d_in[2];
    const float* mus     = (const float*)d_in[3];
    float* out = (float*)d_out;

    int N = in_sizes[1] / DD;   // 500000

    q_kernel<<<1, 128>>>(q, centers, mus, out);
    int blocks = (N + 255) / 256;
    pot_kernel<<<blocks, 256>>>(cand, centers, mus, out + DD, N);
    norm_kernel<<<blocks, 256>>>(out + DD, N);
}

// round 3
// speedup vs baseline: 3.1132x; 3.1132x over previous
#include <cuda_runtime.h>
#include <cuda_bf16.h>
#include <math.h>
#include <cstdint>

#define CC   128      // centers
#define DD   64       // latent dim
#define TILE_M 128    // candidates per CTA
#define EPSF 1e-6f
#define TINV 10.0f    // 1/TEMP
#define DTF  0.1f

__device__ float g_qpot;
__device__ float g_sum;

// ---------------- helpers ----------------
__device__ __forceinline__ uint32_t smem_u32(const void* p) {
    uint32_t a;
    asm("{ .reg .u64 t; cvta.to.shared.u64 t, %1; cvt.u32.u64 %0, t; }" : "=r"(a) : "l"(p));
    return a;
}
__device__ __forceinline__ void ldsm_x4(uint32_t& r0, uint32_t& r1, uint32_t& r2, uint32_t& r3,
                                        uint32_t addr) {
    asm volatile("ldmatrix.sync.aligned.m8n8.x4.shared.b16 {%0,%1,%2,%3}, [%4];"
                 : "=r"(r0), "=r"(r1), "=r"(r2), "=r"(r3) : "r"(addr));
}
__device__ __forceinline__ void mma_bf16(float* c,
                                         uint32_t a0, uint32_t a1, uint32_t a2, uint32_t a3,
                                         uint32_t b0, uint32_t b1) {
    asm volatile("mma.sync.aligned.m16n8k16.row.col.f32.bf16.bf16.f32 "
                 "{%0,%1,%2,%3}, {%4,%5,%6,%7}, {%8,%9}, {%0,%1,%2,%3};"
                 : "+f"(c[0]), "+f"(c[1]), "+f"(c[2]), "+f"(c[3])
                 : "r"(a0), "r"(a1), "r"(a2), "r"(a3), "r"(b0), "r"(b1));
}

// =================== Kernel 1: query flow + q_pot ===================
__global__ void q_kernel(const float* __restrict__ q,
                         const float* __restrict__ centers,
                         const float* __restrict__ mus,
                         float* __restrict__ out) {
    __shared__ float sc[CC * 65];
    __shared__ float qs[DD];
    __shared__ float w[CC];
    __shared__ float rp[4];
    int tid = threadIdx.x;

    if (tid < DD) qs[tid] = q[tid];
    for (int i4 = tid; i4 < CC * DD / 4; i4 += 128) {
        float4 v = ((const float4*)centers)[i4];
        int r = i4 >> 4, c = (i4 & 15) * 4;
        float* dst = sc + r * 65 + c;
        dst[0] = v.x; dst[1] = v.y; dst[2] = v.z; dst[3] = v.w;
    }
    __syncthreads();

    const float* crow = sc + tid * 65;
    float mu = mus[tid];
    float r2 = 0.f;
    #pragma unroll
    for (int d = 0; d < DD; ++d) {
        float df = crow[d] - qs[d];
        r2 = fmaf(df, df, r2);
    }
    r2 = fmaxf(r2, 1e-12f);
    float r = sqrtf(r2);
    float potc = mu / (r + EPSF);
    w[tid] = mu / (r * r * r + EPSF);

    #pragma unroll
    for (int o = 16; o; o >>= 1) potc += __shfl_xor_sync(0xFFFFFFFFu, potc, o);
    if ((tid & 31) == 0) rp[tid >> 5] = potc;
    __syncthreads();
    if (tid == 0) {
        g_qpot = rp[0] + rp[1] + rp[2] + rp[3];
        g_sum  = 0.f;
    }

    if (tid < DD) {
        float qd = qs[tid];
        float s = 0.f;
        #pragma unroll 4
        for (int j = 0; j < CC; ++j)
            s = fmaf(w[j], sc[j * 65 + tid] - qd, s);
        out[tid] = fmaf(DTF, s, qd);
    }
}

// ====== Kernel 2: mma.sync split-bf16 GEMM + potential + exp + sum ======
// dyn smem: 4 x 16KB bf16 tiles (A hi/lo, B hi/lo), 128B-aligned
#define DSMEM_BYTES (4 * 16384 + 128)

__global__ __launch_bounds__(256, 2)
void pot_kernel(const float* __restrict__ cand,
                const float* __restrict__ centers,
                const float* __restrict__ mus,
                float* __restrict__ att, int N) {
    extern __shared__ char dsm[];
    __shared__ float s_zn[TILE_M];
    __shared__ float s_cn[CC];
    __shared__ float s_mu[CC];
    __shared__ float rs[8];

    int tid  = threadIdx.x;
    int lane = tid & 31;
    int wid  = tid >> 5;
    int base = blockIdx.x * TILE_M;

    uint32_t dbase = smem_u32(dsm);
    uint32_t tb = (dbase + 127u) & ~127u;
    char* tiles = dsm + (tb - dbase);
    char* aHi = tiles;
    char* aLo = tiles + 16384;
    char* bHi = tiles + 32768;
    char* bLo = tiles + 49152;

    // ---- convert A (candidates) to bf16 hi/lo, swizzled rows; row norms ----
    #pragma unroll
    for (int it = 0; it < 8; ++it) {
        int idx = tid + 256 * it;             // 0..2047
        int row = idx >> 4, c4 = idx & 15;
        int ri = min(base + row, N - 1);
        float4 v = ((const float4*)cand)[(size_t)ri * 16 + c4];

        __nv_bfloat162 h01 = __floats2bfloat162_rn(v.x, v.y);
        __nv_bfloat162 h23 = __floats2bfloat162_rn(v.z, v.w);
        float rx = v.x - __bfloat162float(__low2bfloat16(h01));
        float ry = v.y - __bfloat162float(__high2bfloat16(h01));
        float rz = v.z - __bfloat162float(__low2bfloat16(h23));
        float rw = v.w - __bfloat162float(__high2bfloat16(h23));
        __nv_bfloat162 l01 = __floats2bfloat162_rn(rx, ry);
        __nv_bfloat162 l23 = __floats2bfloat162_rn(rz, rw);

        // row = 128B; 16B-chunk swizzle: chunk ^= (row & 7)
        uint32_t off = (uint32_t)row * 128u
                     + ((((uint32_t)c4 >> 1) ^ ((uint32_t)row & 7u)) << 4)
                     + ((uint32_t)c4 & 1u) * 8u;
        *(uint2*)(aHi + off) = make_uint2(*(uint32_t*)&h01, *(uint32_t*)&h23);
        *(uint2*)(aLo + off) = make_uint2(*(uint32_t*)&l01, *(uint32_t*)&l23);

        float pz = fmaf(v.x, v.x, fmaf(v.y, v.y, fmaf(v.z, v.z, v.w * v.w)));
        #pragma unroll
        for (int o = 8; o; o >>= 1) pz += __shfl_xor_sync(0xFFFFFFFFu, pz, o);
        if ((tid & 15) == 0) s_zn[row] = pz;
    }

    // ---- convert B (centers) likewise; center norms ----
    #pragma unroll
    for (int it = 0; it < 8; ++it) {
        int idx = tid + 256 * it;
        int row = idx >> 4, c4 = idx & 15;
        float4 v = ((const float4*)centers)[row * 16 + c4];

        __nv_bfloat162 h01 = __floats2bfloat162_rn(v.x, v.y);
        __nv_bfloat162 h23 = __floats2bfloat162_rn(v.z, v.w);
        float rx = v.x - __bfloat162float(__low2bfloat16(h01));
        float ry = v.y - __bfloat162float(__high2bfloat16(h01));
        float rz = v.z - __bfloat162float(__low2bfloat16(h23));
        float rw = v.w - __bfloat162float(__high2bfloat16(h23));
        __nv_bfloat162 l01 = __floats2bfloat162_rn(rx, ry);
        __nv_bfloat162 l23 = __floats2bfloat162_rn(rz, rw);

        uint32_t off = (uint32_t)row * 128u
                     + ((((uint32_t)c4 >> 1) ^ ((uint32_t)row & 7u)) << 4)
                     + ((uint32_t)c4 & 1u) * 8u;
        *(uint2*)(bHi + off) = make_uint2(*(uint32_t*)&h01, *(uint32_t*)&h23);
        *(uint2*)(bLo + off) = make_uint2(*(uint32_t*)&l01, *(uint32_t*)&l23);

        float pc = fmaf(v.x, v.x, fmaf(v.y, v.y, fmaf(v.z, v.z, v.w * v.w)));
        #pragma unroll
        for (int o = 8; o; o >>= 1) pc += __shfl_xor_sync(0xFFFFFFFFu, pc, o);
        if ((tid & 15) == 0) s_cn[row] = pc;
    }
    if (tid < CC) s_mu[tid] = mus[tid];
    __syncthreads();

    // ---- MMA: each warp does M=16 strip x N=128, K=64, 3 splits ----
    int m0 = wid * 16;
    uint32_t rowA = (uint32_t)(m0 + (lane & 15));
    uint32_t aRowOff = rowA * 128u;
    uint32_t hf = (uint32_t)(lane >> 4);           // A k-half chunk select
    uint32_t sA = (uint32_t)(lane & 7);
    uint32_t rowBl = (uint32_t)((((lane >> 4) & 1) << 3) + (lane & 7));
    uint32_t bRowOff = rowBl * 128u;
    uint32_t cbB = (uint32_t)((lane >> 3) & 1);    // B k-half chunk select
    uint32_t sB = (uint32_t)(lane & 7);

    uint32_t aHiU = smem_u32(aHi), aLoU = smem_u32(aLo);
    uint32_t bHiU = smem_u32(bHi), bLoU = smem_u32(bLo);

    float acc[16][4];
    #pragma unroll
    for (int t = 0; t < 16; ++t) {
        acc[t][0] = 0.f; acc[t][1] = 0.f; acc[t][2] = 0.f; acc[t][3] = 0.f;
    }

    #pragma unroll
    for (int s = 0; s < 3; ++s) {
        uint32_t Ab = ((s == 2) ? aLoU : aHiU) + aRowOff;
        uint32_t Bb = ((s == 1) ? bLoU : bHiU) + bRowOff;
        #pragma unroll
        for (int k = 0; k < 4; ++k) {
            uint32_t a0, a1, a2, a3;
            ldsm_x4(a0, a1, a2, a3, Ab + ((((uint32_t)k * 2u + hf) ^ sA) << 4));
            #pragma unroll
            for (int t = 0; t < 8; ++t) {
                uint32_t b0, b1, b2, b3;
                ldsm_x4(b0, b1, b2, b3,
                        Bb + (uint32_t)t * 2048u + ((((uint32_t)k * 2u + cbB) ^ sB) << 4));
                mma_bf16(acc[2 * t],     a0, a1, a2, a3, b0, b1);
                mma_bf16(acc[2 * t + 1], a0, a1, a2, a3, b2, b3);
            }
        }
    }

    // ---- epilogue: pot = sum_j mu_j * rsqrt(zn + cn_j - 2*dot) ----
    int qd = lane & 3, r = lane >> 2;
    float znA = s_zn[m0 + r];
    float znB = s_zn[m0 + r + 8];
    float potA = 0.f, potB = 0.f;
    #pragma unroll
    for (int nt = 0; nt < 16; ++nt) {
        int j0 = nt * 8 + qd * 2;
        float cn0 = s_cn[j0], cn1 = s_cn[j0 + 1];
        float mu0 = s_mu[j0], mu1 = s_mu[j0 + 1];
        float d;
        d = fmaxf(fmaf(acc[nt][0], -2.f, znA + cn0), 1e-12f); potA = fmaf(mu0, rsqrtf(d), potA);
        d = fmaxf(fmaf(acc[nt][1], -2.f, znA + cn1), 1e-12f); potA = fmaf(mu1, rsqrtf(d), potA);
        d = fmaxf(fmaf(acc[nt][2], -2.f, znB + cn0), 1e-12f); potB = fmaf(mu0, rsqrtf(d), potB);
        d = fmaxf(fmaf(acc[nt][3], -2.f, znB + cn1), 1e-12f); potB = fmaf(mu1, rsqrtf(d), potB);
    }
    // quad reduce (lanes sharing same row)
    potA += __shfl_xor_sync(0xFFFFFFFFu, potA, 1);
    potA += __shfl_xor_sync(0xFFFFFFFFu, potA, 2);
    potB += __shfl_xor_sync(0xFFFFFFFFu, potB, 1);
    potB += __shfl_xor_sync(0xFFFFFFFFu, potB, 2);

    float qpot = g_qpot;
    float es = 0.f;
    if (qd == 0) {
        int iA = base + m0 + r;
        int iB = iA + 8;
        if (iA < N) { float e = __expf(-TINV * fabsf(qpot - potA)); att[iA] = e; es += e; }
        if (iB < N) { float e = __expf(-TINV * fabsf(qpot - potB)); att[iB] = e; es += e; }
    }

    // block sum -> atomic
    #pragma unroll
    for (int o = 16; o; o >>= 1) es += __shfl_xor_sync(0xFFFFFFFFu, es, o);
    if (lane == 0) rs[wid] = es;
    __syncthreads();
    if (tid < 8) {
        float v = rs[tid];
        #pragma unroll
        for (int o = 4; o; o >>= 1) v += __shfl_xor_sync(0x000000FFu, v, o);
        if (tid == 0) atomicAdd(&g_sum, v);
    }
}

// ---------- Kernel 3: normalize ----------
__global__ void norm_kernel(float* __restrict__ att, int N) {
    int i = blockIdx.x * blockDim.x + threadIdx.x;
    if (i < N) att[i] *= (1.0f / g_sum);
}

extern "C" void kernel_launch(void* const* d_in, const int* in_sizes, int n_in,
                              void* d_out, int out_size) {
    const float* q       = (const float*)d_in[0];
    const float* cand    = (const float*)d_in[1];
    const float* centers = (const float*)d_in[2];
    const float* mus     = (const float*)d_in[3];
    float* out = (float*)d_out;

    int N = in_sizes[1] / DD;   // 500000

    cudaFuncSetAttribute(pot_kernel, cudaFuncAttributeMaxDynamicSharedMemorySize,
                         DSMEM_BYTES);

    q_kernel<<<1, 128>>>(q, centers, mus, out);
    int tiles = (N + TILE_M - 1) / TILE_M;
    pot_kernel<<<tiles, 256, DSMEM_BYTES>>>(cand, centers, mus, out + DD, N);
    norm_kernel<<<(N + 255) / 256, 256>>>(out + DD, N);
}